// round 13
// baseline (speedup 1.0000x reference)
#include <cuda_runtime.h>
#include <cuda_fp16.h>
#include <math.h>

// Problem constants (fixed by the reference)
#define NMAX   50000
#define EMAX   800000
#define ETOTMAX (EMAX + NMAX)
#define D1     128     // HID*HEADS
#define HEADS  4

// ---------------- scratch (static device globals; no allocation allowed) ----
__device__ __align__(16) __half g_xh_h[NMAX * D1];   // features, fp16 (gather)
__device__ __align__(16) __half g_h_h[NMAX * D1];    // layer-1 output, fp16
__device__ float g_asrc[NMAX * HEADS];
__device__ float g_adst[NMAX * HEADS];
__device__ int   g_cnt[NMAX + 1];
__device__ int   g_off[NMAX + 1];
__device__ int   g_cur[NMAX];
__device__ int   g_srcs[ETOTMAX];
__device__ int   g_bsums[128];
__device__ int   g_is64;

__device__ __forceinline__ int load_idx(const int* ei32, int pos, int is64) {
    return is64 ? ei32[2 * pos] : ei32[pos];
}

// ---------------- CSR build (detect fused into init) ------------------------
__global__ void init_counts(int* cnt, int* cur, int N, const int* __restrict__ ei32) {
    int i = blockIdx.x * blockDim.x + threadIdx.x;
    if (i < N) { cnt[i] = 0; cur[i] = 0; }
    if (i == 0) {
        int any = 0;
        #pragma unroll
        for (int k = 1; k < 128; k += 2) any |= ei32[k];
        g_is64 = (any == 0) ? 1 : 0;
    }
}

__global__ void count_edges(const int* __restrict__ ei32, int E, int N, int* cnt) {
    int e = blockIdx.x * blockDim.x + threadIdx.x;
    int Etot = E + N;
    if (e >= Etot) return;
    int is64 = g_is64;
    int dst = (e < E) ? load_idx(ei32, E + e, is64) : (e - E);
    if (dst < 0 || dst >= N) return;   // defensive
    atomicAdd(&cnt[dst], 1);
}

// phase1: per-block (1024 elems) exclusive scan (block-LOCAL); totals to bsums
__global__ __launch_bounds__(1024)
void scan_phase1(const int* __restrict__ cnt, int* __restrict__ off,
                 int* __restrict__ bsums, int n) {
    __shared__ int warp_sums[32];
    int tid = threadIdx.x;
    int lane = tid & 31, wid = tid >> 5;
    int i = blockIdx.x * 1024 + tid;
    int v = (i < n) ? cnt[i] : 0;
    int x = v;
    #pragma unroll
    for (int ofs = 1; ofs < 32; ofs <<= 1) {
        int y = __shfl_up_sync(0xffffffffu, x, ofs);
        if (lane >= ofs) x += y;
    }
    if (lane == 31) warp_sums[wid] = x;
    __syncthreads();
    if (wid == 0) {
        int ws = warp_sums[lane];
        #pragma unroll
        for (int ofs = 1; ofs < 32; ofs <<= 1) {
            int y = __shfl_up_sync(0xffffffffu, ws, ofs);
            if (lane >= ofs) ws += y;
        }
        warp_sums[lane] = ws;
    }
    __syncthreads();
    int warp_prefix = (wid > 0) ? warp_sums[wid - 1] : 0;
    int incl = x + warp_prefix;
    if (i < n) off[i] = incl - v;
    if (tid == 1023) bsums[blockIdx.x] = incl;
}

// In-block exclusive scan of bsums[0..nb) into sPre (nb <= 64). Call from ALL
// threads (contains __syncthreads) BEFORE any early return.
__device__ __forceinline__ void block_scan_bsums(const int* __restrict__ bsums,
                                                 int nb, int* sPre) {
    int tid = threadIdx.x;
    if (tid < 32) {
        int v0 = (tid < nb) ? bsums[tid] : 0;
        int v1 = (32 + tid < nb) ? bsums[32 + tid] : 0;
        int x0 = v0, x1 = v1;
        #pragma unroll
        for (int o = 1; o < 32; o <<= 1) {
            int y0 = __shfl_up_sync(0xffffffffu, x0, o);
            int y1 = __shfl_up_sync(0xffffffffu, x1, o);
            if (tid >= o) { x0 += y0; x1 += y1; }
        }
        int tot0 = __shfl_sync(0xffffffffu, x0, 31);
        sPre[tid] = x0 - v0;
        sPre[32 + tid] = tot0 + x1 - v1;
    }
    __syncthreads();
}

__global__ void scatter_edges(const int* __restrict__ ei32, int E, int N,
                              const int* __restrict__ off, const int* __restrict__ bsums,
                              int nb, int* cur, int* __restrict__ srcs) {
    __shared__ int sPre[64];
    block_scan_bsums(bsums, nb, sPre);
    int e = blockIdx.x * blockDim.x + threadIdx.x;
    int Etot = E + N;
    if (e >= Etot) return;
    int is64 = g_is64;
    int src, dst;
    if (e < E) { src = load_idx(ei32, e, is64); dst = load_idx(ei32, E + e, is64); }
    else       { src = dst = e - E; }
    if (dst < 0 || dst >= N || src < 0 || src >= N) return;  // defensive
    int pos = atomicAdd(&cur[dst], 1);
    int slot = off[dst] + sPre[dst >> 10] + pos;
    if (slot < 0 || slot >= Etot) return;                    // defensive
    srcs[slot] = src;
}

// ---------------- fp16 HMMA GEMM + fused attn; C stored as fp16 -------------
#define GK 32
#define PA 40    // halfs/row: 20 words ≡ 20 mod 32 -> frag loads conflict-free
#define PB 136   // halfs/row: B scalar-u16 frag loads conflict-free

__device__ __forceinline__ uint2 load4h(const float* A, long idx) {
    float4 v = *(const float4*)(A + idx);
    uint2 r;
    ((__half2*)&r)[0] = __floats2half2_rn(v.x, v.y);
    ((__half2*)&r)[1] = __floats2half2_rn(v.z, v.w);
    return r;
}
__device__ __forceinline__ uint2 load4h(const __half* A, long idx) {
    return *(const uint2*)(A + idx);
}

template <typename TA>
__global__ __launch_bounds__(256)
void gemm_f16_attn(const TA* __restrict__ A, const float* __restrict__ B,
                   __half* __restrict__ C, int M,
                   const float* __restrict__ attS, const float* __restrict__ attD,
                   float* __restrict__ asrc, float* __restrict__ adst) {
    __shared__ __half sA[128 * PA];
    __shared__ __half sB[GK * PB];
    int tid = threadIdx.x;
    int blockRow = blockIdx.x * 128;
    int w = tid >> 5, lane = tid & 31;
    int wm = w >> 1, wn = w & 1;          // warp grid 4x2
    int m0 = wm * 32, n0 = wn * 64;
    int g = lane >> 2, t = lane & 3;

    int r  = tid >> 3;             // A load row 0..31
    int c4 = (tid & 7) * 4;        // A load col (4 halfs/floats)
    int br  = tid >> 5;            // B load row 0..7
    int bc4 = (tid & 31) * 4;      // B load col

    float acc[2][8][4];
    #pragma unroll
    for (int im = 0; im < 2; im++)
        #pragma unroll
        for (int jn = 0; jn < 8; jn++)
            #pragma unroll
            for (int c = 0; c < 4; c++) acc[im][jn][c] = 0.f;

    uint2  rA[4];
    float4 rB[4];
    #pragma unroll
    for (int i = 0; i < 4; i++) {
        int gr = blockRow + i * 32 + r;
        rA[i] = (gr < M) ? load4h(A, (long)gr * 128 + c4) : make_uint2(0u, 0u);
        rB[i] = *(const float4*)(B + (long)(i * 8 + br) * 128 + bc4);
    }

    for (int kc = 0; kc < 128; kc += GK) {
        __syncthreads();
        #pragma unroll
        for (int i = 0; i < 4; i++) {
            *(uint2*)&sA[(i * 32 + r) * PA + c4] = rA[i];
            __half2 h01 = __floats2half2_rn(rB[i].x, rB[i].y);
            __half2 h23 = __floats2half2_rn(rB[i].z, rB[i].w);
            uint2 st;
            st.x = *(unsigned*)&h01; st.y = *(unsigned*)&h23;
            *(uint2*)&sB[(i * 8 + br) * PB + bc4] = st;
        }
        __syncthreads();
        if (kc + GK < 128) {
            int kn = kc + GK;
            #pragma unroll
            for (int i = 0; i < 4; i++) {
                int gr = blockRow + i * 32 + r;
                rA[i] = (gr < M) ? load4h(A, (long)gr * 128 + kn + c4)
                                 : make_uint2(0u, 0u);
                rB[i] = *(const float4*)(B + (long)(kn + i * 8 + br) * 128 + bc4);
            }
        }
        #pragma unroll
        for (int ks = 0; ks < GK; ks += 16) {
            unsigned a[2][4];
            #pragma unroll
            for (int im = 0; im < 2; im++) {
                int r0 = (m0 + im * 16 + g) * PA + ks + 2 * t;
                int r1 = (m0 + im * 16 + 8 + g) * PA + ks + 2 * t;
                a[im][0] = *(const unsigned*)&sA[r0];
                a[im][1] = *(const unsigned*)&sA[r1];
                a[im][2] = *(const unsigned*)&sA[r0 + 8];
                a[im][3] = *(const unsigned*)&sA[r1 + 8];
            }
            #pragma unroll
            for (int jn = 0; jn < 8; jn++) {
                int n = n0 + jn * 8 + g;
                __half2 hb0 = __halves2half2(sB[(ks + 2 * t) * PB + n],
                                             sB[(ks + 2 * t + 1) * PB + n]);
                __half2 hb1 = __halves2half2(sB[(ks + 2 * t + 8) * PB + n],
                                             sB[(ks + 2 * t + 9) * PB + n]);
                unsigned b0 = *(unsigned*)&hb0;
                unsigned b1 = *(unsigned*)&hb1;
                #pragma unroll
                for (int im = 0; im < 2; im++) {
                    asm volatile(
                        "mma.sync.aligned.m16n8k16.row.col.f32.f16.f16.f32 "
                        "{%0,%1,%2,%3}, {%4,%5,%6,%7}, {%8,%9}, {%0,%1,%2,%3};"
                        : "+f"(acc[im][jn][0]), "+f"(acc[im][jn][1]),
                          "+f"(acc[im][jn][2]), "+f"(acc[im][jn][3])
                        : "r"(a[im][0]), "r"(a[im][1]), "r"(a[im][2]), "r"(a[im][3]),
                          "r"(b0), "r"(b1));
                }
            }
        }
    }

    // ---- epilogue: write C as fp16 ----
    #pragma unroll
    for (int im = 0; im < 2; im++) {
        int r0 = blockRow + m0 + im * 16 + g;
        int r1 = r0 + 8;
        #pragma unroll
        for (int jn = 0; jn < 8; jn++) {
            int col = n0 + jn * 8 + t * 2;
            if (r0 < M) *(__half2*)(C + (long)r0 * 128 + col) =
                __floats2half2_rn(acc[im][jn][0], acc[im][jn][1]);
            if (r1 < M) *(__half2*)(C + (long)r1 * 128 + col) =
                __floats2half2_rn(acc[im][jn][2], acc[im][jn][3]);
        }
    }

    // ---- fused attention coefficients (from fp32 accumulators) ----
    #pragma unroll
    for (int im = 0; im < 2; im++) {
        #pragma unroll
        for (int hh = 0; hh < 2; hh++) {
            float s0 = 0.f, s1 = 0.f, d0 = 0.f, d1 = 0.f;
            #pragma unroll
            for (int j = 0; j < 4; j++) {
                int jn = hh * 4 + j;
                int col = n0 + jn * 8 + t * 2;
                float as0 = attS[col], as1 = attS[col + 1];
                float ad0 = attD[col], ad1 = attD[col + 1];
                s0 += acc[im][jn][0] * as0 + acc[im][jn][1] * as1;
                s1 += acc[im][jn][2] * as0 + acc[im][jn][3] * as1;
                d0 += acc[im][jn][0] * ad0 + acc[im][jn][1] * ad1;
                d1 += acc[im][jn][2] * ad0 + acc[im][jn][3] * ad1;
            }
            #pragma unroll
            for (int m = 1; m <= 2; m <<= 1) {
                s0 += __shfl_xor_sync(0xffffffffu, s0, m);
                s1 += __shfl_xor_sync(0xffffffffu, s1, m);
                d0 += __shfl_xor_sync(0xffffffffu, d0, m);
                d1 += __shfl_xor_sync(0xffffffffu, d1, m);
            }
            if (t == 0) {
                int head = wn * 2 + hh;
                int r0 = blockRow + m0 + im * 16 + g;
                int r1 = r0 + 8;
                if (r0 < M) { asrc[r0 * HEADS + head] = s0; adst[r0 * HEADS + head] = d0; }
                if (r1 < M) { asrc[r1 * HEADS + head] = s1; adst[r1 * HEADS + head] = d1; }
            }
        }
    }
}

// fp16 feature fetch: 4 features per lane (8B, coalesced 256B/warp)
__device__ __forceinline__ float4 fetch_feat(const __half* xh, long s, int lane) {
    float2 raw = *(const float2*)(xh + s * 128 + lane * 4);
    const __half2* hp = (const __half2*)&raw;
    float2 lo = __half22float2(hp[0]);
    float2 hi = __half22float2(hp[1]);
    return make_float4(lo.x, lo.y, hi.x, hi.y);
}

// ---- shared gather core: shuffle-distributed indices, depth-4 pipeline -----
// cnt is warp-uniform -> all control flow warp-uniform (full-mask shfl safe).
// Per 32 edges: ONE coalesced index load; per edge: asrc LDG + feature LDG.64.
__device__ __forceinline__ void gat_gather(const __half* __restrict__ xh,
                                           const float* __restrict__ asrc,
                                           const int* __restrict__ sp, int cnt,
                                           int lane, int h, float adst_h,
                                           float4& acc, float& denom) {
    const unsigned FULL = 0xffffffffu;
    int c0 = (lane < cnt) ? sp[lane] : 0;            // indices [0,32)
    int c1 = (32 + lane < cnt) ? sp[32 + lane] : 0;  // indices [32,64)
    int chunk = 0;                                   // c0 covers [chunk*32, ...)

    float  aq[4];
    float4 vq[4];
    #pragma unroll
    for (int k = 0; k < 4; k++) {
        if (k < cnt) {
            int s = __shfl_sync(FULL, c0, k);
            aq[k] = asrc[s * HEADS + h];
            vq[k] = fetch_feat(xh, s, lane);
        }
    }
    for (int i = 0; i < cnt; ++i) {
        int sl = i & 3;
        float a = aq[sl]; float4 v = vq[sl];
        int ip = i + 4;
        if (ip < cnt) {
            int rel = ip - (chunk << 5);
            if (rel >= 64) {                         // rotate chunk registers
                c0 = c1; chunk++;
                int nbase = (chunk << 5) + 32;
                c1 = (nbase + lane < cnt) ? sp[nbase + lane] : 0;
                rel -= 32;
            }
            int s = (rel < 32) ? __shfl_sync(FULL, c0, rel)
                               : __shfl_sync(FULL, c1, rel - 32);
            aq[sl] = asrc[s * HEADS + h];
            vq[sl] = fetch_feat(xh, s, lane);
        }
        float l = a + adst_h;
        l = (l > 0.f) ? l : 0.2f * l;                // leaky relu
        float wgt = __expf(l);
        denom += wgt;
        acc.x += wgt * v.x; acc.y += wgt * v.y;
        acc.z += wgt * v.z; acc.w += wgt * v.w;
    }
}

// ---------------- GAT aggregation layer 1 (fp16 in/out, fp32 accum) ---------
__global__ __launch_bounds__(256)
void gat_aggregate(const __half* __restrict__ xh,
                   const float* __restrict__ asrc,
                   const float* __restrict__ adst,
                   const int* __restrict__ off,
                   const int* __restrict__ bsums, int nb,
                   const int* __restrict__ srcs,
                   const float* __restrict__ bias,
                   __half* __restrict__ out, int N, int Etot) {
    __shared__ int sPre[64];
    block_scan_bsums(bsums, nb, sPre);
    int warp = (blockIdx.x * blockDim.x + threadIdx.x) >> 5;
    if (warp >= N) return;
    int lane = threadIdx.x & 31;
    int h = lane >> 3;
    int n = warp;
    float adst_h = adst[n * HEADS + h];
    int base = off[n] + sPre[n >> 10];
    int end  = (n + 1 < N) ? (off[n + 1] + sPre[(n + 1) >> 10]) : Etot;
    int cnt = end - base;

    float4 acc = make_float4(0.f, 0.f, 0.f, 0.f);
    float denom = 0.f;
    gat_gather(xh, asrc, srcs + base, cnt, lane, h, adst_h, acc, denom);

    float inv = 1.f / (denom + 1e-16f);
    float4 b = *(const float4*)(bias + lane * 4);
    float o0 = fmaxf(acc.x * inv + b.x, 0.f);
    float o1 = fmaxf(acc.y * inv + b.y, 0.f);
    float o2 = fmaxf(acc.z * inv + b.z, 0.f);
    float o3 = fmaxf(acc.w * inv + b.w, 0.f);
    float2 st;
    ((__half2*)&st)[0] = __floats2half2_rn(o0, o1);
    ((__half2*)&st)[1] = __floats2half2_rn(o2, o3);
    *(float2*)(out + (long)n * 128 + lane * 4) = st;
}

// ---------------- layer 2: aggregation + classifier + log_softmax fused -----
__global__ __launch_bounds__(256)
void gat_aggregate_cls(const __half* __restrict__ xh,
                       const float* __restrict__ asrc,
                       const float* __restrict__ adst,
                       const int* __restrict__ off,
                       const int* __restrict__ bsums, int nb,
                       const int* __restrict__ srcs,
                       const float* __restrict__ bias,
                       const float* __restrict__ Wc,
                       const float* __restrict__ bc,
                       float* __restrict__ out, int N, int Etot) {
    __shared__ float sW[128 * 40];
    __shared__ float sb[40];
    __shared__ int sPre[64];
    int tid = threadIdx.x;
    for (int i = tid; i < 128 * 40; i += 256) sW[i] = Wc[i];
    if (tid < 40) sb[tid] = bc[tid];
    block_scan_bsums(bsums, nb, sPre);   // includes __syncthreads (covers sW too)

    int warp = (blockIdx.x * blockDim.x + tid) >> 5;
    if (warp >= N) return;
    int lane = tid & 31;
    int h = lane >> 3;
    int n = warp;
    float adst_h = adst[n * HEADS + h];
    int base = off[n] + sPre[n >> 10];
    int end  = (n + 1 < N) ? (off[n + 1] + sPre[(n + 1) >> 10]) : Etot;
    int cnt = end - base;

    float4 acc = make_float4(0.f, 0.f, 0.f, 0.f);
    float denom = 0.f;
    gat_gather(xh, asrc, srcs + base, cnt, lane, h, adst_h, acc, denom);

    float inv = 1.f / (denom + 1e-16f);
    float4 b = *(const float4*)(bias + lane * 4);
    float hv0 = fmaxf(acc.x * inv + b.x, 0.f);
    float hv1 = fmaxf(acc.y * inv + b.y, 0.f);
    float hv2 = fmaxf(acc.z * inv + b.z, 0.f);
    float hv3 = fmaxf(acc.w * inv + b.w, 0.f);

    // classifier: logits[c] = sum_f h[f] * Wc[f*40+c] + bc[c]
    float acc0 = 0.f, acc1 = 0.f;
    #pragma unroll
    for (int q = 0; q < 32; q++) {
        float f0 = __shfl_sync(0xffffffffu, hv0, q);
        float f1 = __shfl_sync(0xffffffffu, hv1, q);
        float f2 = __shfl_sync(0xffffffffu, hv2, q);
        float f3 = __shfl_sync(0xffffffffu, hv3, q);
        const float* w0 = &sW[(q * 4) * 40];
        acc0 += f0 * w0[lane] + f1 * w0[40 + lane]
              + f2 * w0[80 + lane] + f3 * w0[120 + lane];
        if (lane < 8)
            acc1 += f0 * w0[32 + lane] + f1 * w0[72 + lane]
                  + f2 * w0[112 + lane] + f3 * w0[152 + lane];
    }
    float lv0 = acc0 + sb[lane];
    float lv1 = (lane < 8) ? (acc1 + sb[32 + lane]) : -INFINITY;
    float m = fmaxf(lv0, lv1);
    #pragma unroll
    for (int ofs = 16; ofs; ofs >>= 1) m = fmaxf(m, __shfl_xor_sync(0xffffffffu, m, ofs));
    float s = __expf(lv0 - m) + ((lane < 8) ? __expf(lv1 - m) : 0.f);
    #pragma unroll
    for (int ofs = 16; ofs; ofs >>= 1) s += __shfl_xor_sync(0xffffffffu, s, ofs);
    float lse = m + __logf(s);
    out[(long)n * 40 + lane] = lv0 - lse;
    if (lane < 8) out[(long)n * 40 + 32 + lane] = lv1 - lse;
}

// ---------------- launch ----------------------------------------------------
extern "C" void kernel_launch(void* const* d_in, const int* in_sizes, int n_in,
                              void* d_out, int out_size) {
    const float* x   = (const float*)d_in[0];
    const int*   ei  = (const int*)d_in[1];     // int32 OR int64 (auto-detected)
    const float* W1  = (const float*)d_in[2];
    const float* aS1 = (const float*)d_in[3];
    const float* aD1 = (const float*)d_in[4];
    const float* b1  = (const float*)d_in[5];
    const float* W2  = (const float*)d_in[6];
    const float* aS2 = (const float*)d_in[7];
    const float* aD2 = (const float*)d_in[8];
    const float* b2  = (const float*)d_in[9];
    const float* Wc  = (const float*)d_in[10];
    const float* bc  = (const float*)d_in[11];
    float* out = (float*)d_out;

    int N = in_sizes[0] / 128;
    int E = in_sizes[1] / 2;
    int Etot = E + N;
    int nb = (N + 1023) / 1024;

    __half *p_xh, *p_h;
    float *p_asrc, *p_adst;
    int *p_cnt, *p_off, *p_cur, *p_srcs, *p_bsums;
    cudaGetSymbolAddress((void**)&p_xh,    g_xh_h);
    cudaGetSymbolAddress((void**)&p_h,     g_h_h);
    cudaGetSymbolAddress((void**)&p_asrc,  g_asrc);
    cudaGetSymbolAddress((void**)&p_adst,  g_adst);
    cudaGetSymbolAddress((void**)&p_cnt,   g_cnt);
    cudaGetSymbolAddress((void**)&p_off,   g_off);
    cudaGetSymbolAddress((void**)&p_cur,   g_cur);
    cudaGetSymbolAddress((void**)&p_srcs,  g_srcs);
    cudaGetSymbolAddress((void**)&p_bsums, g_bsums);

    // CSR build (counting sort by destination; self loops folded in)
    init_counts<<<(N + 255) / 256, 256>>>(p_cnt, p_cur, N, ei);
    count_edges<<<(Etot + 255) / 256, 256>>>(ei, E, N, p_cnt);
    scan_phase1<<<nb, 1024>>>(p_cnt, p_off, p_bsums, N);
    scatter_edges<<<(Etot + 255) / 256, 256>>>(ei, E, N, p_off, p_bsums, nb, p_cur, p_srcs);

    int gemmGrid = (N + 127) / 128;
    int aggGrid  = (N * 32 + 255) / 256;

    // Layer 1 (attn fused into GEMM epilogue; features stored fp16)
    gemm_f16_attn<float><<<gemmGrid, 256>>>(x, W1, p_xh, N, aS1, aD1, p_asrc, p_adst);
    gat_aggregate<<<aggGrid, 256>>>(p_xh, p_asrc, p_adst, p_off, p_bsums, nb, p_srcs,
                                    b1, p_h, N, Etot);

    // Layer 2 (A is fp16; aggregation + classifier + log_softmax fused)
    gemm_f16_attn<__half><<<gemmGrid, 256>>>(p_h, W2, p_xh, N, aS2, aD2, p_asrc, p_adst);
    gat_aggregate_cls<<<aggGrid, 256>>>(p_xh, p_asrc, p_adst, p_off, p_bsums, nb, p_srcs,
                                        b2, Wc, bc, out, N, Etot);
}

// round 15
// speedup vs baseline: 1.6805x; 1.6805x over previous
#include <cuda_runtime.h>
#include <cuda_fp16.h>
#include <math.h>

// Problem constants (fixed by the reference)
#define NMAX   50000
#define EMAX   800000
#define ETOTMAX (EMAX + NMAX)
#define D1     128     // HID*HEADS
#define HEADS  4

// ---------------- scratch (static device globals; no allocation allowed) ----
__device__ __align__(16) __half g_xh_h[NMAX * D1];   // features, fp16 (gather)
__device__ __align__(16) __half g_h_h[NMAX * D1];    // layer-1 output, fp16
__device__ float g_asrc[NMAX * HEADS];
__device__ float g_adst[NMAX * HEADS];
__device__ int   g_cnt[NMAX + 1];
__device__ int   g_off[NMAX + 1];
__device__ int   g_cur[NMAX];
__device__ int   g_srcs[ETOTMAX];
__device__ int   g_bsums[128];
__device__ int   g_is64;

__device__ __forceinline__ int load_idx(const int* ei32, int pos, int is64) {
    return is64 ? ei32[2 * pos] : ei32[pos];
}

// ---------------- CSR build (detect fused into init) ------------------------
__global__ void init_counts(int* cnt, int* cur, int N, const int* __restrict__ ei32) {
    int i = blockIdx.x * blockDim.x + threadIdx.x;
    if (i < N) { cnt[i] = 0; cur[i] = 0; }
    if (i == 0) {
        int any = 0;
        #pragma unroll
        for (int k = 1; k < 128; k += 2) any |= ei32[k];
        g_is64 = (any == 0) ? 1 : 0;
    }
}

__global__ void count_edges(const int* __restrict__ ei32, int E, int N, int* cnt) {
    int e = blockIdx.x * blockDim.x + threadIdx.x;
    int Etot = E + N;
    if (e >= Etot) return;
    int is64 = g_is64;
    int dst = (e < E) ? load_idx(ei32, E + e, is64) : (e - E);
    if (dst < 0 || dst >= N) return;   // defensive
    atomicAdd(&cnt[dst], 1);
}

// phase1: per-block (1024 elems) exclusive scan (block-LOCAL); totals to bsums
__global__ __launch_bounds__(1024)
void scan_phase1(const int* __restrict__ cnt, int* __restrict__ off,
                 int* __restrict__ bsums, int n) {
    __shared__ int warp_sums[32];
    int tid = threadIdx.x;
    int lane = tid & 31, wid = tid >> 5;
    int i = blockIdx.x * 1024 + tid;
    int v = (i < n) ? cnt[i] : 0;
    int x = v;
    #pragma unroll
    for (int ofs = 1; ofs < 32; ofs <<= 1) {
        int y = __shfl_up_sync(0xffffffffu, x, ofs);
        if (lane >= ofs) x += y;
    }
    if (lane == 31) warp_sums[wid] = x;
    __syncthreads();
    if (wid == 0) {
        int ws = warp_sums[lane];
        #pragma unroll
        for (int ofs = 1; ofs < 32; ofs <<= 1) {
            int y = __shfl_up_sync(0xffffffffu, ws, ofs);
            if (lane >= ofs) ws += y;
        }
        warp_sums[lane] = ws;
    }
    __syncthreads();
    int warp_prefix = (wid > 0) ? warp_sums[wid - 1] : 0;
    int incl = x + warp_prefix;
    if (i < n) off[i] = incl - v;
    if (tid == 1023) bsums[blockIdx.x] = incl;
}

// In-block exclusive scan of bsums[0..nb) into sPre (nb <= 64). Call from ALL
// threads (contains __syncthreads) BEFORE any early return.
__device__ __forceinline__ void block_scan_bsums(const int* __restrict__ bsums,
                                                 int nb, int* sPre) {
    int tid = threadIdx.x;
    if (tid < 32) {
        int v0 = (tid < nb) ? bsums[tid] : 0;
        int v1 = (32 + tid < nb) ? bsums[32 + tid] : 0;
        int x0 = v0, x1 = v1;
        #pragma unroll
        for (int o = 1; o < 32; o <<= 1) {
            int y0 = __shfl_up_sync(0xffffffffu, x0, o);
            int y1 = __shfl_up_sync(0xffffffffu, x1, o);
            if (tid >= o) { x0 += y0; x1 += y1; }
        }
        int tot0 = __shfl_sync(0xffffffffu, x0, 31);
        sPre[tid] = x0 - v0;
        sPre[32 + tid] = tot0 + x1 - v1;
    }
    __syncthreads();
}

__global__ void scatter_edges(const int* __restrict__ ei32, int E, int N,
                              const int* __restrict__ off, const int* __restrict__ bsums,
                              int nb, int* cur, int* __restrict__ srcs) {
    __shared__ int sPre[64];
    block_scan_bsums(bsums, nb, sPre);
    int e = blockIdx.x * blockDim.x + threadIdx.x;
    int Etot = E + N;
    if (e >= Etot) return;
    int is64 = g_is64;
    int src, dst;
    if (e < E) { src = load_idx(ei32, e, is64); dst = load_idx(ei32, E + e, is64); }
    else       { src = dst = e - E; }
    if (dst < 0 || dst >= N || src < 0 || src >= N) return;  // defensive
    int pos = atomicAdd(&cur[dst], 1);
    int slot = off[dst] + sPre[dst >> 10] + pos;
    if (slot < 0 || slot >= Etot) return;                    // defensive
    srcs[slot] = src;
}

// ---------------- fp16 HMMA GEMM + fused attn; C stored as fp16 -------------
#define GK 32
#define PA 40    // halfs/row: 20 words ≡ 20 mod 32 -> frag loads conflict-free
#define PB 136   // halfs/row: B scalar-u16 frag loads conflict-free

__device__ __forceinline__ uint2 load4h(const float* A, long idx) {
    float4 v = *(const float4*)(A + idx);
    uint2 r;
    ((__half2*)&r)[0] = __floats2half2_rn(v.x, v.y);
    ((__half2*)&r)[1] = __floats2half2_rn(v.z, v.w);
    return r;
}
__device__ __forceinline__ uint2 load4h(const __half* A, long idx) {
    return *(const uint2*)(A + idx);
}

template <typename TA>
__global__ __launch_bounds__(256)
void gemm_f16_attn(const TA* __restrict__ A, const float* __restrict__ B,
                   __half* __restrict__ C, int M,
                   const float* __restrict__ attS, const float* __restrict__ attD,
                   float* __restrict__ asrc, float* __restrict__ adst) {
    __shared__ __half sA[128 * PA];
    __shared__ __half sB[GK * PB];
    int tid = threadIdx.x;
    int blockRow = blockIdx.x * 128;
    int w = tid >> 5, lane = tid & 31;
    int wm = w >> 1, wn = w & 1;          // warp grid 4x2
    int m0 = wm * 32, n0 = wn * 64;
    int g = lane >> 2, t = lane & 3;

    int r  = tid >> 3;             // A load row 0..31
    int c4 = (tid & 7) * 4;        // A load col (4 halfs/floats)
    int br  = tid >> 5;            // B load row 0..7
    int bc4 = (tid & 31) * 4;      // B load col

    float acc[2][8][4];
    #pragma unroll
    for (int im = 0; im < 2; im++)
        #pragma unroll
        for (int jn = 0; jn < 8; jn++)
            #pragma unroll
            for (int c = 0; c < 4; c++) acc[im][jn][c] = 0.f;

    uint2  rA[4];
    float4 rB[4];
    #pragma unroll
    for (int i = 0; i < 4; i++) {
        int gr = blockRow + i * 32 + r;
        rA[i] = (gr < M) ? load4h(A, (long)gr * 128 + c4) : make_uint2(0u, 0u);
        rB[i] = *(const float4*)(B + (long)(i * 8 + br) * 128 + bc4);
    }

    for (int kc = 0; kc < 128; kc += GK) {
        __syncthreads();
        #pragma unroll
        for (int i = 0; i < 4; i++) {
            *(uint2*)&sA[(i * 32 + r) * PA + c4] = rA[i];
            __half2 h01 = __floats2half2_rn(rB[i].x, rB[i].y);
            __half2 h23 = __floats2half2_rn(rB[i].z, rB[i].w);
            uint2 st;
            st.x = *(unsigned*)&h01; st.y = *(unsigned*)&h23;
            *(uint2*)&sB[(i * 8 + br) * PB + bc4] = st;
        }
        __syncthreads();
        if (kc + GK < 128) {
            int kn = kc + GK;
            #pragma unroll
            for (int i = 0; i < 4; i++) {
                int gr = blockRow + i * 32 + r;
                rA[i] = (gr < M) ? load4h(A, (long)gr * 128 + kn + c4)
                                 : make_uint2(0u, 0u);
                rB[i] = *(const float4*)(B + (long)(kn + i * 8 + br) * 128 + bc4);
            }
        }
        #pragma unroll
        for (int ks = 0; ks < GK; ks += 16) {
            unsigned a[2][4];
            #pragma unroll
            for (int im = 0; im < 2; im++) {
                int r0 = (m0 + im * 16 + g) * PA + ks + 2 * t;
                int r1 = (m0 + im * 16 + 8 + g) * PA + ks + 2 * t;
                a[im][0] = *(const unsigned*)&sA[r0];
                a[im][1] = *(const unsigned*)&sA[r1];
                a[im][2] = *(const unsigned*)&sA[r0 + 8];
                a[im][3] = *(const unsigned*)&sA[r1 + 8];
            }
            #pragma unroll
            for (int jn = 0; jn < 8; jn++) {
                int n = n0 + jn * 8 + g;
                __half2 hb0 = __halves2half2(sB[(ks + 2 * t) * PB + n],
                                             sB[(ks + 2 * t + 1) * PB + n]);
                __half2 hb1 = __halves2half2(sB[(ks + 2 * t + 8) * PB + n],
                                             sB[(ks + 2 * t + 9) * PB + n]);
                unsigned b0 = *(unsigned*)&hb0;
                unsigned b1 = *(unsigned*)&hb1;
                #pragma unroll
                for (int im = 0; im < 2; im++) {
                    asm volatile(
                        "mma.sync.aligned.m16n8k16.row.col.f32.f16.f16.f32 "
                        "{%0,%1,%2,%3}, {%4,%5,%6,%7}, {%8,%9}, {%0,%1,%2,%3};"
                        : "+f"(acc[im][jn][0]), "+f"(acc[im][jn][1]),
                          "+f"(acc[im][jn][2]), "+f"(acc[im][jn][3])
                        : "r"(a[im][0]), "r"(a[im][1]), "r"(a[im][2]), "r"(a[im][3]),
                          "r"(b0), "r"(b1));
                }
            }
        }
    }

    // ---- epilogue: write C as fp16 ----
    #pragma unroll
    for (int im = 0; im < 2; im++) {
        int r0 = blockRow + m0 + im * 16 + g;
        int r1 = r0 + 8;
        #pragma unroll
        for (int jn = 0; jn < 8; jn++) {
            int col = n0 + jn * 8 + t * 2;
            if (r0 < M) *(__half2*)(C + (long)r0 * 128 + col) =
                __floats2half2_rn(acc[im][jn][0], acc[im][jn][1]);
            if (r1 < M) *(__half2*)(C + (long)r1 * 128 + col) =
                __floats2half2_rn(acc[im][jn][2], acc[im][jn][3]);
        }
    }

    // ---- fused attention coefficients (from fp32 accumulators) ----
    #pragma unroll
    for (int im = 0; im < 2; im++) {
        #pragma unroll
        for (int hh = 0; hh < 2; hh++) {
            float s0 = 0.f, s1 = 0.f, d0 = 0.f, d1 = 0.f;
            #pragma unroll
            for (int j = 0; j < 4; j++) {
                int jn = hh * 4 + j;
                int col = n0 + jn * 8 + t * 2;
                float as0 = attS[col], as1 = attS[col + 1];
                float ad0 = attD[col], ad1 = attD[col + 1];
                s0 += acc[im][jn][0] * as0 + acc[im][jn][1] * as1;
                s1 += acc[im][jn][2] * as0 + acc[im][jn][3] * as1;
                d0 += acc[im][jn][0] * ad0 + acc[im][jn][1] * ad1;
                d1 += acc[im][jn][2] * ad0 + acc[im][jn][3] * ad1;
            }
            #pragma unroll
            for (int m = 1; m <= 2; m <<= 1) {
                s0 += __shfl_xor_sync(0xffffffffu, s0, m);
                s1 += __shfl_xor_sync(0xffffffffu, s1, m);
                d0 += __shfl_xor_sync(0xffffffffu, d0, m);
                d1 += __shfl_xor_sync(0xffffffffu, d1, m);
            }
            if (t == 0) {
                int head = wn * 2 + hh;
                int r0 = blockRow + m0 + im * 16 + g;
                int r1 = r0 + 8;
                if (r0 < M) { asrc[r0 * HEADS + head] = s0; adst[r0 * HEADS + head] = d0; }
                if (r1 < M) { asrc[r1 * HEADS + head] = s1; adst[r1 * HEADS + head] = d1; }
            }
        }
    }
}

// fp16 feature fetch: 4 features per lane (8B, coalesced 256B/warp)
__device__ __forceinline__ float4 fetch_feat(const __half* xh, long s, int lane) {
    float2 raw = *(const float2*)(xh + s * 128 + lane * 4);
    const __half2* hp = (const __half2*)&raw;
    float2 lo = __half22float2(hp[0]);
    float2 hi = __half22float2(hp[1]);
    return make_float4(lo.x, lo.y, hi.x, hi.y);
}

// ---- gather core: depth-3 pipeline, NAMED registers only (no spills) -------
__device__ __forceinline__ void gat_gather(const __half* __restrict__ xh,
                                           const float* __restrict__ asrc,
                                           const int* __restrict__ sp, int cnt,
                                           int lane, int h, float adst_h,
                                           float4& acc, float& denom) {
    float a0 = 0.f, a1 = 0.f, a2 = 0.f;
    float4 v0 = make_float4(0.f, 0.f, 0.f, 0.f), v1 = v0, v2 = v0;
    if (cnt > 0) {
        int s = sp[0];
        a0 = asrc[s * HEADS + h];
        v0 = fetch_feat(xh, s, lane);
    }
    if (cnt > 1) {
        int s = sp[1];
        a1 = asrc[s * HEADS + h];
        v1 = fetch_feat(xh, s, lane);
    }
    if (cnt > 2) {
        int s = sp[2];
        a2 = asrc[s * HEADS + h];
        v2 = fetch_feat(xh, s, lane);
    }
    for (int i = 0; i < cnt; ++i) {
        float a = a0; float4 v = v0;
        a0 = a1; v0 = v1;
        a1 = a2; v1 = v2;
        if (i + 3 < cnt) {
            int s = sp[i + 3];
            a2 = asrc[s * HEADS + h];
            v2 = fetch_feat(xh, s, lane);
        }
        float l = a + adst_h;
        l = (l > 0.f) ? l : 0.2f * l;     // leaky relu
        float wgt = __expf(l);
        denom += wgt;
        acc.x += wgt * v.x; acc.y += wgt * v.y;
        acc.z += wgt * v.z; acc.w += wgt * v.w;
    }
}

// ---------------- GAT aggregation layer 1 (fp16 in/out, fp32 accum) ---------
__global__ __launch_bounds__(256)
void gat_aggregate(const __half* __restrict__ xh,
                   const float* __restrict__ asrc,
                   const float* __restrict__ adst,
                   const int* __restrict__ off,
                   const int* __restrict__ bsums, int nb,
                   const int* __restrict__ srcs,
                   const float* __restrict__ bias,
                   __half* __restrict__ out, int N, int Etot) {
    __shared__ int sPre[64];
    block_scan_bsums(bsums, nb, sPre);
    int warp = (blockIdx.x * blockDim.x + threadIdx.x) >> 5;
    if (warp >= N) return;
    int lane = threadIdx.x & 31;
    int h = lane >> 3;
    int n = warp;
    float adst_h = adst[n * HEADS + h];
    int base = off[n] + sPre[n >> 10];
    int end  = (n + 1 < N) ? (off[n + 1] + sPre[(n + 1) >> 10]) : Etot;
    int cnt = end - base;

    float4 acc = make_float4(0.f, 0.f, 0.f, 0.f);
    float denom = 0.f;
    gat_gather(xh, asrc, srcs + base, cnt, lane, h, adst_h, acc, denom);

    float inv = 1.f / (denom + 1e-16f);
    float4 b = *(const float4*)(bias + lane * 4);
    float o0 = fmaxf(acc.x * inv + b.x, 0.f);
    float o1 = fmaxf(acc.y * inv + b.y, 0.f);
    float o2 = fmaxf(acc.z * inv + b.z, 0.f);
    float o3 = fmaxf(acc.w * inv + b.w, 0.f);
    float2 st;
    ((__half2*)&st)[0] = __floats2half2_rn(o0, o1);
    ((__half2*)&st)[1] = __floats2half2_rn(o2, o3);
    *(float2*)(out + (long)n * 128 + lane * 4) = st;
}

// ---------------- layer 2: aggregation + classifier + log_softmax fused -----
__global__ __launch_bounds__(256)
void gat_aggregate_cls(const __half* __restrict__ xh,
                       const float* __restrict__ asrc,
                       const float* __restrict__ adst,
                       const int* __restrict__ off,
                       const int* __restrict__ bsums, int nb,
                       const int* __restrict__ srcs,
                       const float* __restrict__ bias,
                       const float* __restrict__ Wc,
                       const float* __restrict__ bc,
                       float* __restrict__ out, int N, int Etot) {
    __shared__ float sW[128 * 40];
    __shared__ float sb[40];
    __shared__ int sPre[64];
    int tid = threadIdx.x;
    for (int i = tid; i < 128 * 40; i += 256) sW[i] = Wc[i];
    if (tid < 40) sb[tid] = bc[tid];
    block_scan_bsums(bsums, nb, sPre);   // includes __syncthreads (covers sW too)

    int warp = (blockIdx.x * blockDim.x + tid) >> 5;
    if (warp >= N) return;
    int lane = tid & 31;
    int h = lane >> 3;
    int n = warp;
    float adst_h = adst[n * HEADS + h];
    int base = off[n] + sPre[n >> 10];
    int end  = (n + 1 < N) ? (off[n + 1] + sPre[(n + 1) >> 10]) : Etot;
    int cnt = end - base;

    float4 acc = make_float4(0.f, 0.f, 0.f, 0.f);
    float denom = 0.f;
    gat_gather(xh, asrc, srcs + base, cnt, lane, h, adst_h, acc, denom);

    float inv = 1.f / (denom + 1e-16f);
    float4 b = *(const float4*)(bias + lane * 4);
    float hv0 = fmaxf(acc.x * inv + b.x, 0.f);
    float hv1 = fmaxf(acc.y * inv + b.y, 0.f);
    float hv2 = fmaxf(acc.z * inv + b.z, 0.f);
    float hv3 = fmaxf(acc.w * inv + b.w, 0.f);

    // classifier: logits[c] = sum_f h[f] * Wc[f*40+c] + bc[c]
    float acc0 = 0.f, acc1 = 0.f;
    #pragma unroll
    for (int q = 0; q < 32; q++) {
        float f0 = __shfl_sync(0xffffffffu, hv0, q);
        float f1 = __shfl_sync(0xffffffffu, hv1, q);
        float f2 = __shfl_sync(0xffffffffu, hv2, q);
        float f3 = __shfl_sync(0xffffffffu, hv3, q);
        const float* w0 = &sW[(q * 4) * 40];
        acc0 += f0 * w0[lane] + f1 * w0[40 + lane]
              + f2 * w0[80 + lane] + f3 * w0[120 + lane];
        if (lane < 8)
            acc1 += f0 * w0[32 + lane] + f1 * w0[72 + lane]
                  + f2 * w0[112 + lane] + f3 * w0[152 + lane];
    }
    float lv0 = acc0 + sb[lane];
    float lv1 = (lane < 8) ? (acc1 + sb[32 + lane]) : -INFINITY;
    float m = fmaxf(lv0, lv1);
    #pragma unroll
    for (int ofs = 16; ofs; ofs >>= 1) m = fmaxf(m, __shfl_xor_sync(0xffffffffu, m, ofs));
    float s = __expf(lv0 - m) + ((lane < 8) ? __expf(lv1 - m) : 0.f);
    #pragma unroll
    for (int ofs = 16; ofs; ofs >>= 1) s += __shfl_xor_sync(0xffffffffu, s, ofs);
    float lse = m + __logf(s);
    out[(long)n * 40 + lane] = lv0 - lse;
    if (lane < 8) out[(long)n * 40 + 32 + lane] = lv1 - lse;
}

// ---------------- launch ----------------------------------------------------
extern "C" void kernel_launch(void* const* d_in, const int* in_sizes, int n_in,
                              void* d_out, int out_size) {
    const float* x   = (const float*)d_in[0];
    const int*   ei  = (const int*)d_in[1];     // int32 OR int64 (auto-detected)
    const float* W1  = (const float*)d_in[2];
    const float* aS1 = (const float*)d_in[3];
    const float* aD1 = (const float*)d_in[4];
    const float* b1  = (const float*)d_in[5];
    const float* W2  = (const float*)d_in[6];
    const float* aS2 = (const float*)d_in[7];
    const float* aD2 = (const float*)d_in[8];
    const float* b2  = (const float*)d_in[9];
    const float* Wc  = (const float*)d_in[10];
    const float* bc  = (const float*)d_in[11];
    float* out = (float*)d_out;

    int N = in_sizes[0] / 128;
    int E = in_sizes[1] / 2;
    int Etot = E + N;
    int nb = (N + 1023) / 1024;

    __half *p_xh, *p_h;
    float *p_asrc, *p_adst;
    int *p_cnt, *p_off, *p_cur, *p_srcs, *p_bsums;
    cudaGetSymbolAddress((void**)&p_xh,    g_xh_h);
    cudaGetSymbolAddress((void**)&p_h,     g_h_h);
    cudaGetSymbolAddress((void**)&p_asrc,  g_asrc);
    cudaGetSymbolAddress((void**)&p_adst,  g_adst);
    cudaGetSymbolAddress((void**)&p_cnt,   g_cnt);
    cudaGetSymbolAddress((void**)&p_off,   g_off);
    cudaGetSymbolAddress((void**)&p_cur,   g_cur);
    cudaGetSymbolAddress((void**)&p_srcs,  g_srcs);
    cudaGetSymbolAddress((void**)&p_bsums, g_bsums);

    // CSR build (counting sort by destination; self loops folded in)
    init_counts<<<(N + 255) / 256, 256>>>(p_cnt, p_cur, N, ei);
    count_edges<<<(Etot + 255) / 256, 256>>>(ei, E, N, p_cnt);
    scan_phase1<<<nb, 1024>>>(p_cnt, p_off, p_bsums, N);
    scatter_edges<<<(Etot + 255) / 256, 256>>>(ei, E, N, p_off, p_bsums, nb, p_cur, p_srcs);

    int gemmGrid = (N + 127) / 128;
    int aggGrid  = (N * 32 + 255) / 256;

    // Layer 1 (attn fused into GEMM epilogue; features stored fp16)
    gemm_f16_attn<float><<<gemmGrid, 256>>>(x, W1, p_xh, N, aS1, aD1, p_asrc, p_adst);
    gat_aggregate<<<aggGrid, 256>>>(p_xh, p_asrc, p_adst, p_off, p_bsums, nb, p_srcs,
                                    b1, p_h, N, Etot);

    // Layer 2 (A is fp16; aggregation + classifier + log_softmax fused)
    gemm_f16_attn<__half><<<gemmGrid, 256>>>(p_h, W2, p_xh, N, aS2, aD2, p_asrc, p_adst);
    gat_aggregate_cls<<<aggGrid, 256>>>(p_xh, p_asrc, p_adst, p_off, p_bsums, nb, p_srcs,
                                        b2, Wc, bc, out, N, Etot);
}

// round 17
// speedup vs baseline: 1.8992x; 1.1302x over previous
#include <cuda_runtime.h>
#include <cuda_fp16.h>
#include <math.h>

// Problem constants (fixed by the reference)
#define NMAX   50000
#define EMAX   800000
#define ETOTMAX (EMAX + NMAX)
#define D1     128     // HID*HEADS
#define HEADS  4

// ---------------- scratch (static device globals; no allocation allowed) ----
__device__ __align__(16) __half g_xh_h[NMAX * D1];   // features, fp16 (gather)
__device__ __align__(16) __half g_h_h[NMAX * D1];    // layer-1 output, fp16
__device__ float g_asrc[NMAX * HEADS];
__device__ float g_adst[NMAX * HEADS];
__device__ int   g_cnt[NMAX + 1];
__device__ int   g_off[NMAX + 1];
__device__ int   g_pos[ETOTMAX];      // per-edge rank within its dst bucket
__device__ int   g_srcs[ETOTMAX];
__device__ int   g_bsums[128];
__device__ int   g_is64;

__device__ __forceinline__ int load_idx(const int* ei32, int pos, int is64) {
    return is64 ? ei32[2 * pos] : ei32[pos];
}

// ---------------- CSR build (detect fused into init) ------------------------
__global__ void init_counts(int* cnt, int N, const int* __restrict__ ei32) {
    int i = blockIdx.x * blockDim.x + threadIdx.x;
    if (i < N) cnt[i] = 0;
    if (i == 0) {
        int any = 0;
        #pragma unroll
        for (int k = 1; k < 128; k += 2) any |= ei32[k];
        g_is64 = (any == 0) ? 1 : 0;
    }
}

// count + record per-edge bucket rank (single atomic pass for the whole build)
__global__ void count_edges(const int* __restrict__ ei32, int E, int N,
                            int* cnt, int* __restrict__ pos) {
    int e = blockIdx.x * blockDim.x + threadIdx.x;
    int Etot = E + N;
    if (e >= Etot) return;
    int is64 = g_is64;
    int dst = (e < E) ? load_idx(ei32, E + e, is64) : (e - E);
    if (dst < 0 || dst >= N) { pos[e] = -1; return; }   // defensive
    pos[e] = atomicAdd(&cnt[dst], 1);
}

// phase1: per-block (1024 elems) exclusive scan (block-LOCAL); totals to bsums
__global__ __launch_bounds__(1024)
void scan_phase1(const int* __restrict__ cnt, int* __restrict__ off,
                 int* __restrict__ bsums, int n) {
    __shared__ int warp_sums[32];
    int tid = threadIdx.x;
    int lane = tid & 31, wid = tid >> 5;
    int i = blockIdx.x * 1024 + tid;
    int v = (i < n) ? cnt[i] : 0;
    int x = v;
    #pragma unroll
    for (int ofs = 1; ofs < 32; ofs <<= 1) {
        int y = __shfl_up_sync(0xffffffffu, x, ofs);
        if (lane >= ofs) x += y;
    }
    if (lane == 31) warp_sums[wid] = x;
    __syncthreads();
    if (wid == 0) {
        int ws = warp_sums[lane];
        #pragma unroll
        for (int ofs = 1; ofs < 32; ofs <<= 1) {
            int y = __shfl_up_sync(0xffffffffu, ws, ofs);
            if (lane >= ofs) ws += y;
        }
        warp_sums[lane] = ws;
    }
    __syncthreads();
    int warp_prefix = (wid > 0) ? warp_sums[wid - 1] : 0;
    int incl = x + warp_prefix;
    if (i < n) off[i] = incl - v;
    if (tid == 1023) bsums[blockIdx.x] = incl;
}

// In-block exclusive scan of bsums[0..nb) into sPre (nb <= 64). Call from ALL
// threads (contains __syncthreads) BEFORE any early return.
__device__ __forceinline__ void block_scan_bsums(const int* __restrict__ bsums,
                                                 int nb, int* sPre) {
    int tid = threadIdx.x;
    if (tid < 32) {
        int v0 = (tid < nb) ? bsums[tid] : 0;
        int v1 = (32 + tid < nb) ? bsums[32 + tid] : 0;
        int x0 = v0, x1 = v1;
        #pragma unroll
        for (int o = 1; o < 32; o <<= 1) {
            int y0 = __shfl_up_sync(0xffffffffu, x0, o);
            int y1 = __shfl_up_sync(0xffffffffu, x1, o);
            if (tid >= o) { x0 += y0; x1 += y1; }
        }
        int tot0 = __shfl_sync(0xffffffffu, x0, 31);
        sPre[tid] = x0 - v0;
        sPre[32 + tid] = tot0 + x1 - v1;
    }
    __syncthreads();
}

// scatter: NO atomics — slot = off[dst] + blockprefix + precomputed rank
__global__ void scatter_edges(const int* __restrict__ ei32, int E, int N,
                              const int* __restrict__ off, const int* __restrict__ bsums,
                              int nb, const int* __restrict__ pos,
                              int* __restrict__ srcs) {
    __shared__ int sPre[64];
    block_scan_bsums(bsums, nb, sPre);
    int e = blockIdx.x * blockDim.x + threadIdx.x;
    int Etot = E + N;
    if (e >= Etot) return;
    int p = pos[e];
    if (p < 0) return;                                       // defensive (bad dst)
    int is64 = g_is64;
    int src, dst;
    if (e < E) { src = load_idx(ei32, e, is64); dst = load_idx(ei32, E + e, is64); }
    else       { src = dst = e - E; }
    if (src < 0 || src >= N) return;                         // defensive
    int slot = off[dst] + sPre[dst >> 10] + p;
    if (slot < 0 || slot >= Etot) return;                    // defensive
    srcs[slot] = src;
}

// ---------------- fp16 HMMA GEMM + fused attn; C stored as fp16 -------------
#define GK 32
#define PA 40    // halfs/row: 20 words ≡ 20 mod 32 -> frag loads conflict-free
#define PB 136   // halfs/row: B scalar-u16 frag loads conflict-free

__device__ __forceinline__ uint2 load4h(const float* A, long idx) {
    float4 v = *(const float4*)(A + idx);
    uint2 r;
    ((__half2*)&r)[0] = __floats2half2_rn(v.x, v.y);
    ((__half2*)&r)[1] = __floats2half2_rn(v.z, v.w);
    return r;
}
__device__ __forceinline__ uint2 load4h(const __half* A, long idx) {
    return *(const uint2*)(A + idx);
}

template <typename TA>
__global__ __launch_bounds__(256)
void gemm_f16_attn(const TA* __restrict__ A, const float* __restrict__ B,
                   __half* __restrict__ C, int M,
                   const float* __restrict__ attS, const float* __restrict__ attD,
                   float* __restrict__ asrc, float* __restrict__ adst) {
    __shared__ __half sA[128 * PA];
    __shared__ __half sB[GK * PB];
    int tid = threadIdx.x;
    int blockRow = blockIdx.x * 128;
    int w = tid >> 5, lane = tid & 31;
    int wm = w >> 1, wn = w & 1;          // warp grid 4x2
    int m0 = wm * 32, n0 = wn * 64;
    int g = lane >> 2, t = lane & 3;

    int r  = tid >> 3;             // A load row 0..31
    int c4 = (tid & 7) * 4;        // A load col (4 halfs/floats)
    int br  = tid >> 5;            // B load row 0..7
    int bc4 = (tid & 31) * 4;      // B load col

    float acc[2][8][4];
    #pragma unroll
    for (int im = 0; im < 2; im++)
        #pragma unroll
        for (int jn = 0; jn < 8; jn++)
            #pragma unroll
            for (int c = 0; c < 4; c++) acc[im][jn][c] = 0.f;

    uint2  rA[4];
    float4 rB[4];
    #pragma unroll
    for (int i = 0; i < 4; i++) {
        int gr = blockRow + i * 32 + r;
        rA[i] = (gr < M) ? load4h(A, (long)gr * 128 + c4) : make_uint2(0u, 0u);
        rB[i] = *(const float4*)(B + (long)(i * 8 + br) * 128 + bc4);
    }

    for (int kc = 0; kc < 128; kc += GK) {
        __syncthreads();
        #pragma unroll
        for (int i = 0; i < 4; i++) {
            *(uint2*)&sA[(i * 32 + r) * PA + c4] = rA[i];
            __half2 h01 = __floats2half2_rn(rB[i].x, rB[i].y);
            __half2 h23 = __floats2half2_rn(rB[i].z, rB[i].w);
            uint2 st;
            st.x = *(unsigned*)&h01; st.y = *(unsigned*)&h23;
            *(uint2*)&sB[(i * 8 + br) * PB + bc4] = st;
        }
        __syncthreads();
        if (kc + GK < 128) {
            int kn = kc + GK;
            #pragma unroll
            for (int i = 0; i < 4; i++) {
                int gr = blockRow + i * 32 + r;
                rA[i] = (gr < M) ? load4h(A, (long)gr * 128 + kn + c4)
                                 : make_uint2(0u, 0u);
                rB[i] = *(const float4*)(B + (long)(kn + i * 8 + br) * 128 + bc4);
            }
        }
        #pragma unroll
        for (int ks = 0; ks < GK; ks += 16) {
            unsigned a[2][4];
            #pragma unroll
            for (int im = 0; im < 2; im++) {
                int r0 = (m0 + im * 16 + g) * PA + ks + 2 * t;
                int r1 = (m0 + im * 16 + 8 + g) * PA + ks + 2 * t;
                a[im][0] = *(const unsigned*)&sA[r0];
                a[im][1] = *(const unsigned*)&sA[r1];
                a[im][2] = *(const unsigned*)&sA[r0 + 8];
                a[im][3] = *(const unsigned*)&sA[r1 + 8];
            }
            #pragma unroll
            for (int jn = 0; jn < 8; jn++) {
                int n = n0 + jn * 8 + g;
                __half2 hb0 = __halves2half2(sB[(ks + 2 * t) * PB + n],
                                             sB[(ks + 2 * t + 1) * PB + n]);
                __half2 hb1 = __halves2half2(sB[(ks + 2 * t + 8) * PB + n],
                                             sB[(ks + 2 * t + 9) * PB + n]);
                unsigned b0 = *(unsigned*)&hb0;
                unsigned b1 = *(unsigned*)&hb1;
                #pragma unroll
                for (int im = 0; im < 2; im++) {
                    asm volatile(
                        "mma.sync.aligned.m16n8k16.row.col.f32.f16.f16.f32 "
                        "{%0,%1,%2,%3}, {%4,%5,%6,%7}, {%8,%9}, {%0,%1,%2,%3};"
                        : "+f"(acc[im][jn][0]), "+f"(acc[im][jn][1]),
                          "+f"(acc[im][jn][2]), "+f"(acc[im][jn][3])
                        : "r"(a[im][0]), "r"(a[im][1]), "r"(a[im][2]), "r"(a[im][3]),
                          "r"(b0), "r"(b1));
                }
            }
        }
    }

    // ---- epilogue: write C as fp16 ----
    #pragma unroll
    for (int im = 0; im < 2; im++) {
        int r0 = blockRow + m0 + im * 16 + g;
        int r1 = r0 + 8;
        #pragma unroll
        for (int jn = 0; jn < 8; jn++) {
            int col = n0 + jn * 8 + t * 2;
            if (r0 < M) *(__half2*)(C + (long)r0 * 128 + col) =
                __floats2half2_rn(acc[im][jn][0], acc[im][jn][1]);
            if (r1 < M) *(__half2*)(C + (long)r1 * 128 + col) =
                __floats2half2_rn(acc[im][jn][2], acc[im][jn][3]);
        }
    }

    // ---- fused attention coefficients (from fp32 accumulators) ----
    #pragma unroll
    for (int im = 0; im < 2; im++) {
        #pragma unroll
        for (int hh = 0; hh < 2; hh++) {
            float s0 = 0.f, s1 = 0.f, d0 = 0.f, d1 = 0.f;
            #pragma unroll
            for (int j = 0; j < 4; j++) {
                int jn = hh * 4 + j;
                int col = n0 + jn * 8 + t * 2;
                float as0 = attS[col], as1 = attS[col + 1];
                float ad0 = attD[col], ad1 = attD[col + 1];
                s0 += acc[im][jn][0] * as0 + acc[im][jn][1] * as1;
                s1 += acc[im][jn][2] * as0 + acc[im][jn][3] * as1;
                d0 += acc[im][jn][0] * ad0 + acc[im][jn][1] * ad1;
                d1 += acc[im][jn][2] * ad0 + acc[im][jn][3] * ad1;
            }
            #pragma unroll
            for (int m = 1; m <= 2; m <<= 1) {
                s0 += __shfl_xor_sync(0xffffffffu, s0, m);
                s1 += __shfl_xor_sync(0xffffffffu, s1, m);
                d0 += __shfl_xor_sync(0xffffffffu, d0, m);
                d1 += __shfl_xor_sync(0xffffffffu, d1, m);
            }
            if (t == 0) {
                int head = wn * 2 + hh;
                int r0 = blockRow + m0 + im * 16 + g;
                int r1 = r0 + 8;
                if (r0 < M) { asrc[r0 * HEADS + head] = s0; adst[r0 * HEADS + head] = d0; }
                if (r1 < M) { asrc[r1 * HEADS + head] = s1; adst[r1 * HEADS + head] = d1; }
            }
        }
    }
}

// fp16 feature fetch: 4 features per lane (8B, coalesced 256B/warp)
__device__ __forceinline__ float4 fetch_feat(const __half* xh, long s, int lane) {
    float2 raw = *(const float2*)(xh + s * 128 + lane * 4);
    const __half2* hp = (const __half2*)&raw;
    float2 lo = __half22float2(hp[0]);
    float2 hi = __half22float2(hp[1]);
    return make_float4(lo.x, lo.y, hi.x, hi.y);
}

// ---- gather core: depth-2 pipeline (measured-best at 221.2us) --------------
__device__ __forceinline__ void gat_gather(const __half* __restrict__ xh,
                                           const float* __restrict__ asrc,
                                           const int* __restrict__ sp, int cnt,
                                           int lane, int h, float adst_h,
                                           float4& acc, float& denom) {
    float a0 = 0.f, a1 = 0.f;
    float4 v0 = make_float4(0.f, 0.f, 0.f, 0.f), v1 = v0;
    if (cnt > 0) {
        int s = sp[0];
        a0 = asrc[s * HEADS + h];
        v0 = fetch_feat(xh, s, lane);
    }
    if (cnt > 1) {
        int s = sp[1];
        a1 = asrc[s * HEADS + h];
        v1 = fetch_feat(xh, s, lane);
    }
    for (int i = 0; i < cnt; ++i) {
        float a = a0; float4 v = v0;
        a0 = a1; v0 = v1;
        if (i + 2 < cnt) {
            int s = sp[i + 2];
            a1 = asrc[s * HEADS + h];
            v1 = fetch_feat(xh, s, lane);
        }
        float l = a + adst_h;
        l = (l > 0.f) ? l : 0.2f * l;     // leaky relu
        float wgt = __expf(l);
        denom += wgt;
        acc.x += wgt * v.x; acc.y += wgt * v.y;
        acc.z += wgt * v.z; acc.w += wgt * v.w;
    }
}

// ---------------- GAT aggregation layer 1 (fp16 in/out, fp32 accum) ---------
__global__ __launch_bounds__(256)
void gat_aggregate(const __half* __restrict__ xh,
                   const float* __restrict__ asrc,
                   const float* __restrict__ adst,
                   const int* __restrict__ off,
                   const int* __restrict__ bsums, int nb,
                   const int* __restrict__ srcs,
                   const float* __restrict__ bias,
                   __half* __restrict__ out, int N, int Etot) {
    __shared__ int sPre[64];
    block_scan_bsums(bsums, nb, sPre);
    int warp = (blockIdx.x * blockDim.x + threadIdx.x) >> 5;
    if (warp >= N) return;
    int lane = threadIdx.x & 31;
    int h = lane >> 3;
    int n = warp;
    float adst_h = adst[n * HEADS + h];
    int base = off[n] + sPre[n >> 10];
    int end  = (n + 1 < N) ? (off[n + 1] + sPre[(n + 1) >> 10]) : Etot;
    int cnt = end - base;

    float4 acc = make_float4(0.f, 0.f, 0.f, 0.f);
    float denom = 0.f;
    gat_gather(xh, asrc, srcs + base, cnt, lane, h, adst_h, acc, denom);

    float inv = 1.f / (denom + 1e-16f);
    float4 b = *(const float4*)(bias + lane * 4);
    float o0 = fmaxf(acc.x * inv + b.x, 0.f);
    float o1 = fmaxf(acc.y * inv + b.y, 0.f);
    float o2 = fmaxf(acc.z * inv + b.z, 0.f);
    float o3 = fmaxf(acc.w * inv + b.w, 0.f);
    float2 st;
    ((__half2*)&st)[0] = __floats2half2_rn(o0, o1);
    ((__half2*)&st)[1] = __floats2half2_rn(o2, o3);
    *(float2*)(out + (long)n * 128 + lane * 4) = st;
}

// ---------------- layer 2: aggregation + classifier + log_softmax fused -----
__global__ __launch_bounds__(256)
void gat_aggregate_cls(const __half* __restrict__ xh,
                       const float* __restrict__ asrc,
                       const float* __restrict__ adst,
                       const int* __restrict__ off,
                       const int* __restrict__ bsums, int nb,
                       const int* __restrict__ srcs,
                       const float* __restrict__ bias,
                       const float* __restrict__ Wc,
                       const float* __restrict__ bc,
                       float* __restrict__ out, int N, int Etot) {
    __shared__ float sW[128 * 40];
    __shared__ float sb[40];
    __shared__ int sPre[64];
    int tid = threadIdx.x;
    for (int i = tid; i < 128 * 40; i += 256) sW[i] = Wc[i];
    if (tid < 40) sb[tid] = bc[tid];
    block_scan_bsums(bsums, nb, sPre);   // includes __syncthreads (covers sW too)

    int warp = (blockIdx.x * blockDim.x + tid) >> 5;
    if (warp >= N) return;
    int lane = tid & 31;
    int h = lane >> 3;
    int n = warp;
    float adst_h = adst[n * HEADS + h];
    int base = off[n] + sPre[n >> 10];
    int end  = (n + 1 < N) ? (off[n + 1] + sPre[(n + 1) >> 10]) : Etot;
    int cnt = end - base;

    float4 acc = make_float4(0.f, 0.f, 0.f, 0.f);
    float denom = 0.f;
    gat_gather(xh, asrc, srcs + base, cnt, lane, h, adst_h, acc, denom);

    float inv = 1.f / (denom + 1e-16f);
    float4 b = *(const float4*)(bias + lane * 4);
    float hv0 = fmaxf(acc.x * inv + b.x, 0.f);
    float hv1 = fmaxf(acc.y * inv + b.y, 0.f);
    float hv2 = fmaxf(acc.z * inv + b.z, 0.f);
    float hv3 = fmaxf(acc.w * inv + b.w, 0.f);

    // classifier: logits[c] = sum_f h[f] * Wc[f*40+c] + bc[c]
    float acc0 = 0.f, acc1 = 0.f;
    #pragma unroll
    for (int q = 0; q < 32; q++) {
        float f0 = __shfl_sync(0xffffffffu, hv0, q);
        float f1 = __shfl_sync(0xffffffffu, hv1, q);
        float f2 = __shfl_sync(0xffffffffu, hv2, q);
        float f3 = __shfl_sync(0xffffffffu, hv3, q);
        const float* w0 = &sW[(q * 4) * 40];
        acc0 += f0 * w0[lane] + f1 * w0[40 + lane]
              + f2 * w0[80 + lane] + f3 * w0[120 + lane];
        if (lane < 8)
            acc1 += f0 * w0[32 + lane] + f1 * w0[72 + lane]
                  + f2 * w0[112 + lane] + f3 * w0[152 + lane];
    }
    float lv0 = acc0 + sb[lane];
    float lv1 = (lane < 8) ? (acc1 + sb[32 + lane]) : -INFINITY;
    float m = fmaxf(lv0, lv1);
    #pragma unroll
    for (int ofs = 16; ofs; ofs >>= 1) m = fmaxf(m, __shfl_xor_sync(0xffffffffu, m, ofs));
    float s = __expf(lv0 - m) + ((lane < 8) ? __expf(lv1 - m) : 0.f);
    #pragma unroll
    for (int ofs = 16; ofs; ofs >>= 1) s += __shfl_xor_sync(0xffffffffu, s, ofs);
    float lse = m + __logf(s);
    out[(long)n * 40 + lane] = lv0 - lse;
    if (lane < 8) out[(long)n * 40 + 32 + lane] = lv1 - lse;
}

// ---------------- launch ----------------------------------------------------
extern "C" void kernel_launch(void* const* d_in, const int* in_sizes, int n_in,
                              void* d_out, int out_size) {
    const float* x   = (const float*)d_in[0];
    const int*   ei  = (const int*)d_in[1];     // int32 OR int64 (auto-detected)
    const float* W1  = (const float*)d_in[2];
    const float* aS1 = (const float*)d_in[3];
    const float* aD1 = (const float*)d_in[4];
    const float* b1  = (const float*)d_in[5];
    const float* W2  = (const float*)d_in[6];
    const float* aS2 = (const float*)d_in[7];
    const float* aD2 = (const float*)d_in[8];
    const float* b2  = (const float*)d_in[9];
    const float* Wc  = (const float*)d_in[10];
    const float* bc  = (const float*)d_in[11];
    float* out = (float*)d_out;

    int N = in_sizes[0] / 128;
    int E = in_sizes[1] / 2;
    int Etot = E + N;
    int nb = (N + 1023) / 1024;

    __half *p_xh, *p_h;
    float *p_asrc, *p_adst;
    int *p_cnt, *p_off, *p_pos, *p_srcs, *p_bsums;
    cudaGetSymbolAddress((void**)&p_xh,    g_xh_h);
    cudaGetSymbolAddress((void**)&p_h,     g_h_h);
    cudaGetSymbolAddress((void**)&p_asrc,  g_asrc);
    cudaGetSymbolAddress((void**)&p_adst,  g_adst);
    cudaGetSymbolAddress((void**)&p_cnt,   g_cnt);
    cudaGetSymbolAddress((void**)&p_off,   g_off);
    cudaGetSymbolAddress((void**)&p_pos,   g_pos);
    cudaGetSymbolAddress((void**)&p_srcs,  g_srcs);
    cudaGetSymbolAddress((void**)&p_bsums, g_bsums);

    // CSR build: ONE atomic pass (count+rank), scan, atomic-free scatter
    init_counts<<<(N + 255) / 256, 256>>>(p_cnt, N, ei);
    count_edges<<<(Etot + 255) / 256, 256>>>(ei, E, N, p_cnt, p_pos);
    scan_phase1<<<nb, 1024>>>(p_cnt, p_off, p_bsums, N);
    scatter_edges<<<(Etot + 255) / 256, 256>>>(ei, E, N, p_off, p_bsums, nb, p_pos, p_srcs);

    int gemmGrid = (N + 127) / 128;
    int aggGrid  = (N * 32 + 255) / 256;

    // Layer 1 (attn fused into GEMM epilogue; features stored fp16)
    gemm_f16_attn<float><<<gemmGrid, 256>>>(x, W1, p_xh, N, aS1, aD1, p_asrc, p_adst);
    gat_aggregate<<<aggGrid, 256>>>(p_xh, p_asrc, p_adst, p_off, p_bsums, nb, p_srcs,
                                    b1, p_h, N, Etot);

    // Layer 2 (A is fp16; aggregation + classifier + log_softmax fused)
    gemm_f16_attn<__half><<<gemmGrid, 256>>>(p_h, W2, p_xh, N, aS2, aD2, p_asrc, p_adst);
    gat_aggregate_cls<<<aggGrid, 256>>>(p_xh, p_asrc, p_adst, p_off, p_bsums, nb, p_srcs,
                                        b2, Wc, bc, out, N, Etot);
}